// round 2
// baseline (speedup 1.0000x reference)
#include <cuda_runtime.h>

// heightfield: [16, 1, 512, 512] float32 -> output same shape.
// out[w] = 1 - clip( max_{r=1..16}( pad(row)[w+r] - r/10 ) - row[w], 0, 1 )
// Rewritten as sliding-window max of g[x] = s[x] - (x-base)/10 via Gil-Werman
// prefix/suffix decomposition: each thread owns one 16-block, all in registers.

#define IM 512
#define RADIUS 16
#define PAD_VAL (-1000.0f)
#define BLKS_PER_ROW (IM / RADIUS)   // 32
#define THREADS 256

__global__ void shadow_gw(const float* __restrict__ in, float* __restrict__ out) {
    const int gtid = blockIdx.x * blockDim.x + threadIdx.x;
    const int row = gtid >> 5;          // 32 threads per row
    const int b   = gtid & 31;          // 16-element block within row
    const int base = b * RADIUS;

    const float* rp = in + (size_t)row * IM;
    float* op = out + (size_t)row * IM;

    // ---- load current block (16 floats) and next block (16 floats) ----
    float cur[RADIUS];
    float nxt[RADIUS];
    const float4* rp4 = reinterpret_cast<const float4*>(rp + base);
    #pragma unroll
    for (int i = 0; i < 4; ++i) {
        float4 v = rp4[i];
        cur[4*i+0] = v.x; cur[4*i+1] = v.y; cur[4*i+2] = v.z; cur[4*i+3] = v.w;
    }
    if (b < BLKS_PER_ROW - 1) {
        #pragma unroll
        for (int i = 0; i < 4; ++i) {
            float4 v = rp4[4 + i];
            nxt[4*i+0] = v.x; nxt[4*i+1] = v.y; nxt[4*i+2] = v.z; nxt[4*i+3] = v.w;
        }
    } else {
        #pragma unroll
        for (int j = 0; j < RADIUS; ++j) nxt[j] = PAD_VAL;
    }

    // ---- g values: g[u] = s[base+u] - 0.1*u, u in [0,32) ----
    // suffix max of g over current block (in place)
    float S[RADIUS];
    #pragma unroll
    for (int j = 0; j < RADIUS; ++j) S[j] = fmaf((float)j, -0.1f, cur[j]);
    #pragma unroll
    for (int j = RADIUS - 2; j >= 0; --j) S[j] = fmaxf(S[j], S[j + 1]);

    // prefix max of g over next block (in place)
    float P[RADIUS];
    #pragma unroll
    for (int j = 0; j < RADIUS; ++j) P[j] = fmaf((float)(RADIUS + j), -0.1f, nxt[j]);
    #pragma unroll
    for (int j = 1; j < RADIUS; ++j) P[j] = fmaxf(P[j], P[j - 1]);

    // ---- outputs: w = base + j ----
    // window u in [j+1, j+16]: j<15 -> max(S[j+1], P[j]); j=15 -> P[15]
    float res[RADIUS];
    #pragma unroll
    for (int j = 0; j < RADIUS; ++j) {
        float m = (j < RADIUS - 1) ? fmaxf(S[j + 1], P[j]) : P[RADIUS - 1];
        float compare = fmaf((float)j, 0.1f, m);      // + (w-base)/10
        float d = compare - cur[j];
        d = fminf(fmaxf(d, 0.0f), 1.0f);
        res[j] = 1.0f - d;
    }

    float4* op4 = reinterpret_cast<float4*>(op + base);
    #pragma unroll
    for (int i = 0; i < 4; ++i)
        op4[i] = make_float4(res[4*i+0], res[4*i+1], res[4*i+2], res[4*i+3]);
}

extern "C" void kernel_launch(void* const* d_in, const int* in_sizes, int n_in,
                              void* d_out, int out_size) {
    const float* in = (const float*)d_in[0];
    float* out = (float*)d_out;
    const int rows = in_sizes[0] / IM;               // 8192
    const int total = rows * BLKS_PER_ROW;           // 262144 threads
    shadow_gw<<<total / THREADS, THREADS>>>(in, out);
}

// round 3
// speedup vs baseline: 1.2950x; 1.2950x over previous
#include <cuda_runtime.h>

// heightfield: [16,1,512,512] f32 -> same shape.
// out[w] = 1 - clip( max_{r=1..16}( pad(row)[w+r] - r/10 ) - row[w], 0, 1 )
// Gil-Werman window-max in registers; smem staging with stride-17 block padding
// so both the global access pattern (coalesced float4) and the per-thread
// block reads (conflict-free scalar LDS) are fast.

#define IM 512
#define RADIUS 16
#define PAD_VAL (-1000.0f)
#define ROWS_PER_CTA 8
#define THREADS (ROWS_PER_CTA * 32)
#define BSTRIDE 17                    // 16-elem block + 1 pad
#define IN_ROW (33 * BSTRIDE)         // 33 blocks (32 data + 1 pad block) = 561
#define RES_ROW (32 * BSTRIDE)        // 544

__device__ __forceinline__ int sidx(int b, int j) { return b * BSTRIDE + j; }

__global__ __launch_bounds__(THREADS) void shadow_gw2(const float* __restrict__ in,
                                                      float* __restrict__ out) {
    __shared__ float sin_[ROWS_PER_CTA][IN_ROW];
    __shared__ float sres[ROWS_PER_CTA][RES_ROW];

    const int w = threadIdx.x >> 5;        // warp == row within CTA
    const int t = threadIdx.x & 31;        // lane == 16-block index
    const int row = blockIdx.x * ROWS_PER_CTA + w;

    const float* rp = in + (size_t)row * IM;
    float* op = out + (size_t)row * IM;

    // ---- coalesced load, scatter into padded smem ----
    #pragma unroll
    for (int i = 0; i < 4; ++i) {
        const int e = 4 * (t + 32 * i);               // element offset in row
        float4 v = reinterpret_cast<const float4*>(rp)[t + 32 * i];
        float* d = &sin_[w][sidx(e >> 4, e & 15)];    // 4 scalars stay in one block
        d[0] = v.x; d[1] = v.y; d[2] = v.z; d[3] = v.w;
    }
    if (t < RADIUS) sin_[w][sidx(32, t)] = PAD_VAL;   // right pad block
    __syncthreads();

    // ---- per-thread Gil-Werman on blocks t (cur) and t+1 (next) ----
    float gc[RADIUS], S[RADIUS], P[RADIUS];
    #pragma unroll
    for (int j = 0; j < RADIUS; ++j)
        gc[j] = fmaf((float)j, -0.1f, sin_[w][sidx(t, j)]);
    #pragma unroll
    for (int j = 0; j < RADIUS; ++j)
        P[j] = fmaf((float)(RADIUS + j), -0.1f, sin_[w][sidx(t + 1, j)]);

    S[RADIUS - 1] = gc[RADIUS - 1];
    #pragma unroll
    for (int j = RADIUS - 2; j >= 0; --j) S[j] = fmaxf(gc[j], S[j + 1]);
    #pragma unroll
    for (int j = 1; j < RADIUS; ++j) P[j] = fmaxf(P[j], P[j - 1]);

    #pragma unroll
    for (int j = 0; j < RADIUS; ++j) {
        float m = (j < RADIUS - 1) ? fmaxf(S[j + 1], P[j]) : P[RADIUS - 1];
        float d = m - gc[j];                          // (m+0.1j) - (gc[j]+0.1j)
        d = fminf(fmaxf(d, 0.0f), 1.0f);
        sres[w][sidx(t, j)] = 1.0f - d;
    }
    __syncthreads();

    // ---- gather from padded smem, coalesced store ----
    #pragma unroll
    for (int i = 0; i < 4; ++i) {
        const int e = 4 * (t + 32 * i);
        const float* s = &sres[w][sidx(e >> 4, e & 15)];
        reinterpret_cast<float4*>(op)[t + 32 * i] = make_float4(s[0], s[1], s[2], s[3]);
    }
}

extern "C" void kernel_launch(void* const* d_in, const int* in_sizes, int n_in,
                              void* d_out, int out_size) {
    const float* in = (const float*)d_in[0];
    float* out = (float*)d_out;
    const int rows = in_sizes[0] / IM;                 // 8192
    shadow_gw2<<<rows / ROWS_PER_CTA, THREADS>>>(in, out);
}

// round 4
// speedup vs baseline: 1.5735x; 1.2151x over previous
#include <cuda_runtime.h>

// heightfield: [16,1,512,512] f32 -> same shape.
// out[w] = 1 - clip( max_{r=1..16}( pad(row)[w+r] - r/10 ) - row[w], 0, 1 )
// g[x] = s[x] - 0.1*x  (per-row column x). Then d = max(g[w+1..w+16]) - g[w].
// Warp = 112 outputs, 128 loaded inputs (no halo needed). Per-lane quad
// aggregates + 7 shuffles. No shared memory, no barriers.

#define IM 512
#define RADIUS 16
#define PAD_VAL (-1000.0f)
#define WARPS_PER_ROW 5      // 112*4 + 64
#define OUT_PER_WARP 112
#define THREADS 256

__global__ __launch_bounds__(THREADS) void shadow_shfl(const float* __restrict__ in,
                                                       float* __restrict__ out) {
    const int gw = blockIdx.x * (THREADS / 32) + (threadIdx.x >> 5);
    const int l  = threadIdx.x & 31;
    const int row  = gw / WARPS_PER_ROW;
    const int wseg = gw - row * WARPS_PER_ROW;
    const int b    = wseg * OUT_PER_WARP;          // column base of this warp
    const int c0   = b + 4 * l;                    // this lane's quad column

    const float* rp = in + (size_t)row * IM;
    float* op = out + (size_t)row * IM;

    // ---- load quad (pad beyond row end) ----
    float g0, g1, g2, g3;
    if (c0 < IM) {
        float4 v = *reinterpret_cast<const float4*>(rp + c0);
        g0 = fmaf((float)(c0 + 0), -0.1f, v.x);
        g1 = fmaf((float)(c0 + 1), -0.1f, v.y);
        g2 = fmaf((float)(c0 + 2), -0.1f, v.z);
        g3 = fmaf((float)(c0 + 3), -0.1f, v.w);
    } else {
        g0 = g1 = g2 = g3 = PAD_VAL;
    }

    // ---- per-quad aggregates ----
    const float S2 = fmaxf(g2, g3);
    const float S1 = fmaxf(g1, S2);
    const float M  = fmaxf(g0, S1);        // full quad max
    const float P1 = fmaxf(g0, g1);
    const float P2 = fmaxf(P1, g2);
    // P0 = g0, P3 = M

    // ---- 7 shuffles: M from l+1..l+3, prefixes from l+4 ----
    const unsigned FULL = 0xffffffffu;
    const float M1  = __shfl_down_sync(FULL, M, 1);
    const float M2  = __shfl_down_sync(FULL, M, 2);
    const float M3  = __shfl_down_sync(FULL, M, 3);
    const float P0r = __shfl_down_sync(FULL, g0, 4);
    const float P1r = __shfl_down_sync(FULL, P1, 4);
    const float P2r = __shfl_down_sync(FULL, P2, 4);
    const float P3r = __shfl_down_sync(FULL, M, 4);

    const float C = fmaxf(M1, fmaxf(M2, M3));      // quads l+1..l+3

    // window maxes for outputs c0+j, j=0..3
    const float m0 = fmaxf(fmaxf(S1, C), P0r);
    const float m1 = fmaxf(fmaxf(S2, C), P1r);
    const float m2 = fmaxf(fmaxf(g3, C), P2r);
    const float m3 = fmaxf(C, P3r);

    float4 o;
    o.x = 1.0f - fminf(fmaxf(m0 - g0, 0.0f), 1.0f);
    o.y = 1.0f - fminf(fmaxf(m1 - g1, 0.0f), 1.0f);
    o.z = 1.0f - fminf(fmaxf(m2 - g2, 0.0f), 1.0f);
    o.w = 1.0f - fminf(fmaxf(m3 - g3, 0.0f), 1.0f);

    if (l < OUT_PER_WARP / 4 && c0 < IM)
        *reinterpret_cast<float4*>(op + c0) = o;
}

extern "C" void kernel_launch(void* const* d_in, const int* in_sizes, int n_in,
                              void* d_out, int out_size) {
    const float* in = (const float*)d_in[0];
    float* out = (float*)d_out;
    const int rows = in_sizes[0] / IM;                       // 8192
    const int total_warps = rows * WARPS_PER_ROW;            // 40960
    const int ctas = (total_warps * 32 + THREADS - 1) / THREADS;  // 5120
    shadow_shfl<<<ctas, THREADS>>>(in, out);
}